// round 6
// baseline (speedup 1.0000x reference)
#include <cuda_runtime.h>

// Inverse 3D Haar synthesis:
//   in  : [B=2, 8*16, T=8, H=128, W=128] fp32 (8 subbands of 16 channels)
//   out : [B=2, 16, 16, 256, 256] fp32
// out[b,g,2t+pt,2h+ph,2w+pw] = (1/8) * sum_s (-1)^(bt*pt+bh*ph+bw*pw) * x[b, s*16+g, t, h, w]
// with s = 4*bt + 2*bh + bw.
//
// One thread owns 4 consecutive input w (8x LDG.128: 512B/warp dense streams).
// Each warp covers a full input W row (128 w) -> a full output row (256 floats,
// 1KB) per (pt,ph). The interleaved output would force stride-32B stores, so a
// warp-local smem exchange re-permutes to two fully-dense STG.128 (16B/lane).

__device__ __forceinline__ float4 f4add(float4 a, float4 b) {
    return make_float4(a.x + b.x, a.y + b.y, a.z + b.z, a.w + b.w);
}
__device__ __forceinline__ float4 f4sub(float4 a, float4 b) {
    return make_float4(a.x - b.x, a.y - b.y, a.z - b.z, a.w - b.w);
}

__global__ __launch_bounds__(256) void ihaar3d_kernel(const float* __restrict__ x,
                                                      float* __restrict__ out) {
    __shared__ float4 sbuf[8][64];  // 1KB per warp

    // Decode: [b(1)][g(4)][t(3)][h(7)][w4(5)] bits -> 2^20 threads.
    const int idx  = blockIdx.x * blockDim.x + threadIdx.x;
    const int lane = threadIdx.x & 31;   // == w4
    const int warp = threadIdx.x >> 5;
    const int h = (idx >> 5) & 127;
    const int t = (idx >> 12) & 7;
    const int g = (idx >> 15) & 15;
    const int b = (idx >> 19) & 1;

    // input: [B, 128, 8, 128, 128]; subband stride = 16 channels. Offsets fit int32.
    const int SUB = 16 * 8 * 128 * 128;  // 2,097,152
    const int base = (((b * 128 + g) * 8 + t) * 128 + h) * 128 + (lane << 2);

    float4 v0 = *reinterpret_cast<const float4*>(x + base + 0 * SUB);  // lll
    float4 v1 = *reinterpret_cast<const float4*>(x + base + 1 * SUB);  // llh
    float4 v2 = *reinterpret_cast<const float4*>(x + base + 2 * SUB);  // lhl
    float4 v3 = *reinterpret_cast<const float4*>(x + base + 3 * SUB);  // lhh
    float4 v4 = *reinterpret_cast<const float4*>(x + base + 4 * SUB);  // hll
    float4 v5 = *reinterpret_cast<const float4*>(x + base + 5 * SUB);  // hlh
    float4 v6 = *reinterpret_cast<const float4*>(x + base + 6 * SUB);  // hhl
    float4 v7 = *reinterpret_cast<const float4*>(x + base + 7 * SUB);  // hhh

    // Stage 1: W butterfly (bit0).
    float4 ll_e = f4add(v0, v1), ll_o = f4sub(v0, v1);
    float4 lh_e = f4add(v2, v3), lh_o = f4sub(v2, v3);
    float4 hl_e = f4add(v4, v5), hl_o = f4sub(v4, v5);
    float4 hh_e = f4add(v6, v7), hh_o = f4sub(v6, v7);

    // Stage 2: H butterfly (bit1): index = ph.
    float4 le[2] = {f4add(ll_e, lh_e), f4sub(ll_e, lh_e)};
    float4 lo[2] = {f4add(ll_o, lh_o), f4sub(ll_o, lh_o)};
    float4 he[2] = {f4add(hl_e, hh_e), f4sub(hl_e, hh_e)};
    float4 ho[2] = {f4add(hl_o, hh_o), f4sub(hl_o, hh_o)};

    // Stage 3: T butterfly (bit2) + scale + warp exchange + dense store.
    // out: [2, 16, 16, 256, 256]; offsets fit int32. Warp row = 256 floats (1KB).
    const float k = 0.125f;
    const int orow0 = (((b * 16 + g) * 16 + 2 * t) * 256 + 2 * h) * 256;
    const int PT = 256 * 256;
    const int PH = 256;

#pragma unroll
    for (int pt = 0; pt < 2; ++pt) {
#pragma unroll
        for (int ph = 0; ph < 2; ++ph) {
            float4 e = pt == 0 ? f4add(le[ph], he[ph]) : f4sub(le[ph], he[ph]);
            float4 o = pt == 0 ? f4add(lo[ph], ho[ph]) : f4sub(lo[ph], ho[ph]);
            // Lane's 32B of interleaved output, split into two 16B chunks.
            float4 c_lo = make_float4(e.x * k, o.x * k, e.y * k, o.y * k);
            float4 c_hi = make_float4(e.z * k, o.z * k, e.w * k, o.w * k);
            sbuf[warp][2 * lane]     = c_lo;
            sbuf[warp][2 * lane + 1] = c_hi;
            __syncwarp();
            float4 d0 = sbuf[warp][lane];
            float4 d1 = sbuf[warp][lane + 32];
            __syncwarp();
            const int orow = orow0 + pt * PT + ph * PH;
            *reinterpret_cast<float4*>(out + orow + 4 * lane)       = d0;
            *reinterpret_cast<float4*>(out + orow + 128 + 4 * lane) = d1;
        }
    }
}

extern "C" void kernel_launch(void* const* d_in, const int* in_sizes, int n_in,
                              void* d_out, int out_size) {
    const float* x = (const float*)d_in[0];
    float* out = (float*)d_out;
    // total threads = 2*16*8*128*32 = 1,048,576
    ihaar3d_kernel<<<4096, 256>>>(x, out);
}